// round 1
// baseline (speedup 1.0000x reference)
#include <cuda_runtime.h>
#include <math.h>

#define D 32
#define H 128
#define THREADS 128
#define ROWS_PER_CTA 256   // 128 threads x 2 rows

typedef unsigned long long u64;

__device__ __forceinline__ u64 pack2(float lo, float hi) {
    u64 r;
    asm("mov.b64 %0, {%1, %2};" : "=l"(r) : "f"(lo), "f"(hi));
    return r;
}
__device__ __forceinline__ void unpack2(u64 p, float& lo, float& hi) {
    asm("mov.b64 {%0, %1}, %2;" : "=f"(lo), "=f"(hi) : "l"(p));
}
// Packed dual-fp32 FMA (Blackwell f32x2 path; 2x FFMA throughput per issue slot)
__device__ __forceinline__ u64 fma2(u64 a, u64 b, u64 c) {
    u64 d;
    asm("fma.rn.f32x2 %0, %1, %2, %3;" : "=l"(d) : "l"(a), "l"(b), "l"(c));
    return d;
}

__device__ __forceinline__ float tanh_fast(float z) {
    float az = fabsf(z);
    float e  = __expf(-2.0f * az);              // MUFU.EX2 based
    float t  = __fdividef(1.0f - e, 1.0f + e);  // MUFU.RCP based
    return copysignf(t, z);
}

// Dynamic SMEM layout:
//   w1r[H*D]  : u64  {W1[i][k], W1[i][k]}   at [k*D + i]
//   w2r[H*D]  : u64  {W2[k][i], W2[k][i]}   at [k*D + i]
//   b1r[H]    : u64  replicated b1
//   b2r[D]    : u64  replicated b2
//   cs[H]     : f32  c_k = sum_i W1[i,k]*W2[k,i]
#define SMEM_BYTES ((H*D + H*D + H + D) * 8 + H * 4)

extern "C" __global__ void __launch_bounds__(THREADS, 3)
stein_kernel(const float* __restrict__ x,
             const float* __restrict__ W1,
             const float* __restrict__ b1,
             const float* __restrict__ W2,
             const float* __restrict__ b2,
             const float* __restrict__ theta,
             float* __restrict__ out)
{
    extern __shared__ u64 smem[];
    u64*   w1r = smem;
    u64*   w2r = w1r + H * D;
    u64*   b1r = w2r + H * D;
    u64*   b2r = b1r + H;
    float* cs  = (float*)(b2r + D);

    const int tid = threadIdx.x;

    // ---- stage weights (replicated pairs), conflict-free SMEM writes ----
    #pragma unroll
    for (int idx = tid; idx < H * D; idx += THREADS) {
        int k = idx / D, i = idx % D;
        float w = W1[i * H + k];          // transpose read (L2-resident, tiny)
        w1r[idx] = pack2(w, w);
    }
    #pragma unroll
    for (int idx = tid; idx < H * D; idx += THREADS) {
        float w = W2[idx];                // already [k][i] contiguous
        w2r[idx] = pack2(w, w);
    }
    if (tid < H) {
        float v = b1[tid];
        b1r[tid] = pack2(v, v);
        float c = 0.0f;
        #pragma unroll
        for (int i = 0; i < D; i++)
            c += W1[i * H + tid] * W2[tid * D + i];
        cs[tid] = c;
    }
    if (tid < D) {
        float v = b2[tid];
        b2r[tid] = pack2(v, v);
    }
    __syncthreads();

    // ---- per-thread: two rows packed into f32x2 lanes ----
    const int r0 = blockIdx.x * ROWS_PER_CTA + tid;
    const int r1 = r0 + THREADS;
    const float* xa = x + (size_t)r0 * D;
    const float* xb = x + (size_t)r1 * D;

    u64 xv[D];
    #pragma unroll
    for (int i = 0; i < D; i += 4) {
        float4 a = *(const float4*)(xa + i);
        float4 b = *(const float4*)(xb + i);
        xv[i + 0] = pack2(a.x, b.x);
        xv[i + 1] = pack2(a.y, b.y);
        xv[i + 2] = pack2(a.z, b.z);
        xv[i + 3] = pack2(a.w, b.w);
    }

    const float th = theta[0];

    // -x . b2 term (packed)
    u64 tb = pack2(0.0f, 0.0f);
    #pragma unroll
    for (int i = 0; i < D; i++) tb = fma2(xv[i], b2r[i], tb);
    float acc0, acc1;
    unpack2(tb, acc0, acc1);
    acc0 = -acc0;
    acc1 = -acc1;

    // main loop over hidden units
    #pragma unroll 2
    for (int k = 0; k < H; k++) {
        const u64* w1p = w1r + k * D;
        const u64* w2p = w2r + k * D;
        u64 z = b1r[k];
        u64 v = pack2(0.0f, 0.0f);
        #pragma unroll
        for (int i = 0; i < D; i++) {
            z = fma2(xv[i], w1p[i], z);
            v = fma2(xv[i], w2p[i], v);
        }
        float z0, z1, v0, v1;
        unpack2(z, z0, z1);
        unpack2(v, v0, v1);
        float h0 = tanh_fast(z0);
        float h1 = tanh_fast(z1);
        float ck = cs[k];
        float g0 = fmaf(-h0, h0, 1.0f);
        float g1 = fmaf(-h1, h1, 1.0f);
        acc0 = fmaf(g0, ck, acc0);
        acc1 = fmaf(g1, ck, acc1);
        acc0 = fmaf(-h0, v0, acc0);
        acc1 = fmaf(-h1, v1, acc1);
    }

    out[r0] = acc0 + th;
    out[r1] = acc1 + th;
}

extern "C" void kernel_launch(void* const* d_in, const int* in_sizes, int n_in,
                              void* d_out, int out_size)
{
    const float* x     = (const float*)d_in[0];
    const float* W1    = (const float*)d_in[1];
    const float* b1    = (const float*)d_in[2];
    const float* W2    = (const float*)d_in[3];
    const float* b2    = (const float*)d_in[4];
    const float* theta = (const float*)d_in[5];
    float*       out   = (float*)d_out;

    const int nrows = in_sizes[0] / D;            // 65536
    const int grid  = nrows / ROWS_PER_CTA;       // 256

    cudaFuncSetAttribute(stein_kernel,
                         cudaFuncAttributeMaxDynamicSharedMemorySize,
                         SMEM_BYTES);
    stein_kernel<<<grid, THREADS, SMEM_BYTES>>>(x, W1, b1, W2, b2, theta, out);
}

// round 3
// speedup vs baseline: 2.4495x; 2.4495x over previous
#include <cuda_runtime.h>
#include <cuda_bf16.h>
#include <cstdint>
#include <math.h>

#define D 32
#define H 128
#define THREADS 128
#define TILE_M 64           // rows per CTA
#define NROWS 65536

// Precomputed B fragments in exact m16n8k16 HMMA fragment order.
// Index: ((((nt*2 + ks)*2 + hl)*32 + lane)*2 + j)
//   nt 0..15 : z GEMM (B[n][k] = W1[k][n]),  nt 16..31 : v GEMM (B[n][k] = W2[n][k])
//   ks : K-step (K=32 -> 2 steps of 16), hl : 0=hi bf16, 1=lo bf16
__device__ uint32_t g_Bf[32 * 2 * 2 * 32 * 2];   // 32 KB
__device__ float    g_cs[H];                     // c_k = sum_i W1[i,k] * W2[k,i]

__device__ __forceinline__ uint32_t pack_bf16(__nv_bfloat16 a, __nv_bfloat16 b) {
    return (uint32_t)__bfloat16_as_ushort(a) | ((uint32_t)__bfloat16_as_ushort(b) << 16);
}
__device__ __forceinline__ void split2(float vx, float vy, uint32_t& hi, uint32_t& lo) {
    __nv_bfloat16 hx = __float2bfloat16_rn(vx);
    __nv_bfloat16 hy = __float2bfloat16_rn(vy);
    float rx = vx - __bfloat162float(hx);
    float ry = vy - __bfloat162float(hy);
    hi = pack_bf16(hx, hy);
    lo = pack_bf16(__float2bfloat16_rn(rx), __float2bfloat16_rn(ry));
}
__device__ __forceinline__ float tanh_ap(float x) {
    float y;
    asm("tanh.approx.f32 %0, %1;" : "=f"(y) : "f"(x));
    return y;
}
__device__ __forceinline__ void mma_bf16(float* d, const uint32_t* a, uint32_t b0, uint32_t b1) {
    asm volatile(
        "mma.sync.aligned.m16n8k16.row.col.f32.bf16.bf16.f32 "
        "{%0,%1,%2,%3}, {%4,%5,%6,%7}, {%8,%9}, {%0,%1,%2,%3};"
        : "+f"(d[0]), "+f"(d[1]), "+f"(d[2]), "+f"(d[3])
        : "r"(a[0]), "r"(a[1]), "r"(a[2]), "r"(a[3]), "r"(b0), "r"(b1));
}

// ---------------- prep kernel: build B frags + c_k once ----------------
extern "C" __global__ void stein_prep(const float* __restrict__ W1,
                                      const float* __restrict__ W2)
{
    int idx = blockIdx.x * blockDim.x + threadIdx.x;   // 0..8191
    if (idx < 8192) {
        int j  = idx & 1;
        int l  = (idx >> 1) & 31;
        int hl = (idx >> 6) & 1;
        int ks = (idx >> 7) & 1;
        int nt = idx >> 8;
        int n  = nt * 8 + (l >> 2);                 // 0..255 over [z | v]
        int k0 = ks * 16 + 2 * (l & 3) + j * 8;     // first of the k pair
        float w0, w1;
        if (nt < 16) {                              // z: B[n][k] = W1[k][n]
            w0 = W1[k0 * H + n];
            w1 = W1[(k0 + 1) * H + n];
        } else {                                    // v: B[n][k] = W2[n'][k]
            int np = n - H;
            w0 = W2[np * D + k0];
            w1 = W2[np * D + k0 + 1];
        }
        uint32_t hi, lo;
        split2(w0, w1, hi, lo);
        g_Bf[idx] = hl ? lo : hi;
    }
    if (idx < H) {
        float c = 0.0f;
        #pragma unroll
        for (int i = 0; i < D; i++)
            c += W1[i * H + idx] * W2[idx * D + i];
        g_cs[idx] = c;
    }
}

// ---------------- main kernel ----------------
extern "C" __global__ void __launch_bounds__(THREADS, 1)
stein_main(const float* __restrict__ x,
           const float* __restrict__ b1,
           const float* __restrict__ b2,
           const float* __restrict__ theta,
           float* __restrict__ out)
{
    __shared__ float s_base[TILE_M];
    __shared__ float s_part[TILE_M][2];

    const int tid  = threadIdx.x;
    const int lane = tid & 31;
    const int w    = tid >> 5;
    const int mh   = w >> 1;        // row half (0: rows 0-31, 1: rows 32-63)
    const int kh   = w & 1;         // hidden-unit half (cols 0-63 / 64-127)
    const int row0 = blockIdx.x * TILE_M;

    // ---- prologue: s_base[r] = theta - x[r].b2 (exact fp32) ----
    if (tid < TILE_M) {
        const float4* xr  = (const float4*)(x + (size_t)(row0 + tid) * D);
        const float4* b2v = (const float4*)b2;
        float s = __ldg(theta);
        #pragma unroll
        for (int i = 0; i < D / 4; i++) {
            float4 a = __ldg(xr + i);
            float4 b = __ldg(b2v + i);
            s = fmaf(-a.x, b.x, s);
            s = fmaf(-a.y, b.y, s);
            s = fmaf(-a.z, b.z, s);
            s = fmaf(-a.w, b.w, s);
        }
        s_base[tid] = s;
    }

    // ---- A fragments straight from gmem (frag-order loads, hi/lo split) ----
    const int Mbase = row0 + mh * 32;
    uint32_t a_hi[2][2][4], a_lo[2][2][4];
    #pragma unroll
    for (int mt = 0; mt < 2; mt++) {
        const int r = Mbase + mt * 16 + (lane >> 2);
        #pragma unroll
        for (int ks = 0; ks < 2; ks++) {
            const int c = ks * 16 + 2 * (lane & 3);
            float2 v00 = __ldg((const float2*)(x + (size_t)r       * D + c));
            float2 v10 = __ldg((const float2*)(x + (size_t)(r + 8) * D + c));
            float2 v01 = __ldg((const float2*)(x + (size_t)r       * D + c + 8));
            float2 v11 = __ldg((const float2*)(x + (size_t)(r + 8) * D + c + 8));
            split2(v00.x, v00.y, a_hi[mt][ks][0], a_lo[mt][ks][0]);
            split2(v10.x, v10.y, a_hi[mt][ks][1], a_lo[mt][ks][1]);
            split2(v01.x, v01.y, a_hi[mt][ks][2], a_lo[mt][ks][2]);
            split2(v11.x, v11.y, a_hi[mt][ks][3], a_lo[mt][ks][3]);
        }
    }

    // ---- mainloop: z and v GEMMs, 3-pass bf16 emulation ----
    float acc[2][2][8][4];   // [zv][mt][p][frag]
    #pragma unroll
    for (int zv = 0; zv < 2; zv++)
        #pragma unroll
        for (int mt = 0; mt < 2; mt++)
            #pragma unroll
            for (int p = 0; p < 8; p++)
                #pragma unroll
                for (int e = 0; e < 4; e++)
                    acc[zv][mt][p][e] = 0.0f;

    #pragma unroll
    for (int p = 0; p < 8; p++) {
        const int ntz = kh * 8 + p;
        const int ntv = 16 + kh * 8 + p;
        uint2 bz[2][2], bv[2][2];   // [ks][hl]
        #pragma unroll
        for (int ks = 0; ks < 2; ks++)
            #pragma unroll
            for (int hl = 0; hl < 2; hl++) {
                bz[ks][hl] = *(const uint2*)&g_Bf[(((ntz * 2 + ks) * 2 + hl) * 32 + lane) * 2];
                bv[ks][hl] = *(const uint2*)&g_Bf[(((ntv * 2 + ks) * 2 + hl) * 32 + lane) * 2];
            }
        #pragma unroll
        for (int mt = 0; mt < 2; mt++)
            #pragma unroll
            for (int ks = 0; ks < 2; ks++) {
                mma_bf16(acc[0][mt][p], a_hi[mt][ks], bz[ks][0].x, bz[ks][0].y); // hi*hi
                mma_bf16(acc[1][mt][p], a_hi[mt][ks], bv[ks][0].x, bv[ks][0].y);
                mma_bf16(acc[0][mt][p], a_hi[mt][ks], bz[ks][1].x, bz[ks][1].y); // hi*lo
                mma_bf16(acc[1][mt][p], a_hi[mt][ks], bv[ks][1].x, bv[ks][1].y);
                mma_bf16(acc[0][mt][p], a_lo[mt][ks], bz[ks][0].x, bz[ks][0].y); // lo*hi
                mma_bf16(acc[1][mt][p], a_lo[mt][ks], bv[ks][0].x, bv[ks][0].y);
            }
    }

    // ---- epilogue: h = tanh(z + b1), psum += (1-h^2)c_k - h*v ----
    float psum[4] = {0.f, 0.f, 0.f, 0.f};
    #pragma unroll
    for (int p = 0; p < 8; p++) {
        #pragma unroll
        for (int j = 0; j < 2; j++) {
            const int k = kh * 64 + p * 8 + 2 * (lane & 3) + j;
            const float b1k = __ldg(b1 + k);
            const float ck  = g_cs[k];
            #pragma unroll
            for (int mt = 0; mt < 2; mt++)
                #pragma unroll
                for (int rs = 0; rs < 2; rs++) {
                    float z = acc[0][mt][p][rs * 2 + j] + b1k;
                    float v = acc[1][mt][p][rs * 2 + j];
                    float h = tanh_ap(z);
                    float g = fmaf(-h, h, 1.0f);
                    float& ps = psum[mt * 2 + rs];
                    ps = fmaf(g, ck, ps);
                    ps = fmaf(-h, v, ps);
                }
        }
    }
    // quad reduction over the 4 lanes sharing the same rows
    #pragma unroll
    for (int i = 0; i < 4; i++) {
        psum[i] += __shfl_xor_sync(0xFFFFFFFFu, psum[i], 1);
        psum[i] += __shfl_xor_sync(0xFFFFFFFFu, psum[i], 2);
    }
    if ((lane & 3) == 0) {
        const int rbase = mh * 32 + (lane >> 2);
        s_part[rbase +  0][kh] = psum[0];   // mt0, row r
        s_part[rbase +  8][kh] = psum[1];   // mt0, row r+8
        s_part[rbase + 16][kh] = psum[2];   // mt1, row r
        s_part[rbase + 24][kh] = psum[3];   // mt1, row r+8
    }
    __syncthreads();

    if (tid < TILE_M)
        out[row0 + tid] = s_base[tid] + s_part[tid][0] + s_part[tid][1];
}

extern "C" void kernel_launch(void* const* d_in, const int* in_sizes, int n_in,
                              void* d_out, int out_size)
{
    const float* x     = (const float*)d_in[0];
    const float* W1    = (const float*)d_in[1];
    const float* b1    = (const float*)d_in[2];
    const float* W2    = (const float*)d_in[3];
    const float* b2    = (const float*)d_in[4];
    const float* theta = (const float*)d_in[5];
    float*       out   = (float*)d_out;

    const int nrows = in_sizes[0] / D;          // 65536
    const int grid  = nrows / TILE_M;           // 1024

    stein_prep<<<32, 256>>>(W1, W2);
    stein_main<<<grid, THREADS>>>(x, b1, b2, theta, out);
}